// round 3
// baseline (speedup 1.0000x reference)
#include <cuda_runtime.h>

// fastmax attention, b=4 h=16 n=1024 d=64, fp32 SIMT baseline.
// Decomposition:
//   prep:   Qn = q / ||q||, Kn = k / ||k||, Vp = v + 0.1*noise
//   qr:     QR[bh][i][m] = Qn_i . rpe2[m],  rpe2 = rpe_matrix[n-1:]   (causal: m <= i)
//   main:   S = 1 + Qn Kn^T + QR[i][i-j]  (masked to j<=i),  out = S Vp / rowsum(S)

#define B_  4
#define H_  16
#define N_  1024
#define D_  64
#define BH_ (B_*H_)

// Scratch (device globals: allocation-free per harness rules)
__device__ float g_qn[(size_t)BH_ * N_ * D_];           // 16 MB
__device__ float g_kn[(size_t)BH_ * N_ * D_];           // 16 MB
__device__ float g_vp[(size_t)BH_ * N_ * D_];           // 16 MB
__device__ float g_qr[(size_t)BH_ * N_ * N_];           // 256 MB

// ---------------------------------------------------------------------------
// prep: row-normalize q and k (one warp per 64-float row)
// ---------------------------------------------------------------------------
__global__ void prep_norm_kernel(const float* __restrict__ q,
                                 const float* __restrict__ k) {
    int gw   = (blockIdx.x * blockDim.x + threadIdx.x) >> 5;
    int lane = threadIdx.x & 31;
    const int total = BH_ * N_;
    const float* src;
    float* dst;
    int row;
    if (gw < total) { src = q; dst = g_qn; row = gw; }
    else            { src = k; dst = g_kn; row = gw - total; }
    const float2 v = reinterpret_cast<const float2*>(src + (size_t)row * D_)[lane];
    float ss = v.x * v.x + v.y * v.y;
    #pragma unroll
    for (int o = 16; o > 0; o >>= 1) ss += __shfl_xor_sync(0xffffffffu, ss, o);
    float inv = rsqrtf(ss);
    float2 r; r.x = v.x * inv; r.y = v.y * inv;
    reinterpret_cast<float2*>(dst + (size_t)row * D_)[lane] = r;
}

// ---------------------------------------------------------------------------
// prep: Vp = v + 0.1 * drop_noise (vectorized elementwise)
// ---------------------------------------------------------------------------
__global__ void prep_v_kernel(const float* __restrict__ v,
                              const float* __restrict__ nz) {
    int i = blockIdx.x * blockDim.x + threadIdx.x;
    float4 a = reinterpret_cast<const float4*>(v)[i];
    float4 b = reinterpret_cast<const float4*>(nz)[i];
    a.x = fmaf(0.1f, b.x, a.x);
    a.y = fmaf(0.1f, b.y, a.y);
    a.z = fmaf(0.1f, b.z, a.z);
    a.w = fmaf(0.1f, b.w, a.w);
    reinterpret_cast<float4*>(g_vp)[i] = a;
}

// ---------------------------------------------------------------------------
// QR[bh][i][m] = Qn[bh][i] . rpe2[m]   (64x64 tiles, lower-triangular tiles only)
// block = 256 threads = 16x16, each thread computes a 4x4 micro-tile
// ---------------------------------------------------------------------------
__global__ void __launch_bounds__(256) qr_kernel(const float* __restrict__ rpe) {
    if (blockIdx.x > blockIdx.y) return;   // m-tile must be <= i-tile
    const int m0 = blockIdx.x * 64;
    const int i0 = blockIdx.y * 64;
    const int bh = blockIdx.z;

    __shared__ float Qt[64 * 65];   // transposed: [kdim][row]
    __shared__ float Rt[64 * 65];   // transposed: [kdim][mrow]

    const int tid = threadIdx.x;
    const int tx = tid & 15, ty = tid >> 4;

    const float* qsrc = g_qn + ((size_t)bh * N_ + i0) * D_;
    const float* rsrc = rpe + (size_t)(N_ - 1 + m0) * D_;

    #pragma unroll
    for (int t = tid; t < 1024; t += 256) {
        int r = t >> 4, c = (t & 15) << 2;
        float4 x = *reinterpret_cast<const float4*>(qsrc + r * D_ + c);
        Qt[(c + 0) * 65 + r] = x.x; Qt[(c + 1) * 65 + r] = x.y;
        Qt[(c + 2) * 65 + r] = x.z; Qt[(c + 3) * 65 + r] = x.w;
        float4 y = *reinterpret_cast<const float4*>(rsrc + r * D_ + c);
        Rt[(c + 0) * 65 + r] = y.x; Rt[(c + 1) * 65 + r] = y.y;
        Rt[(c + 2) * 65 + r] = y.z; Rt[(c + 3) * 65 + r] = y.w;
    }
    __syncthreads();

    float acc[4][4] = {};
    #pragma unroll 8
    for (int kk = 0; kk < 64; kk++) {
        float a[4], b[4];
        #pragma unroll
        for (int u = 0; u < 4; u++) a[u] = Qt[kk * 65 + 4 * ty + u];
        #pragma unroll
        for (int w = 0; w < 4; w++) b[w] = Rt[kk * 65 + 4 * tx + w];
        #pragma unroll
        for (int u = 0; u < 4; u++)
            #pragma unroll
            for (int w = 0; w < 4; w++)
                acc[u][w] = fmaf(a[u], b[w], acc[u][w]);
    }

    float* dst = g_qr + (size_t)bh * N_ * N_;
    #pragma unroll
    for (int u = 0; u < 4; u++) {
        float4 o4 = make_float4(acc[u][0], acc[u][1], acc[u][2], acc[u][3]);
        *reinterpret_cast<float4*>(dst + (size_t)(i0 + 4 * ty + u) * N_ + m0 + 4 * tx) = o4;
    }
}

// ---------------------------------------------------------------------------
// Main fused attention: one block per (bh, i-tile). 64x64 tiles, causal loop
// over j-tiles. Two smem GEMMs per tile + bias gather from g_qr.
// ---------------------------------------------------------------------------
__global__ void __launch_bounds__(256) fastmax_main_kernel(float* __restrict__ out) {
    extern __shared__ float sm[];
    float* Qt = sm;             // [64][65] transposed (kdim-major)
    float* Kt = sm + 4160;      // [64][65] transposed
    float* Ss = sm + 8320;      // [64][65] row-major scores
    float* Vs = sm + 12480;     // [64][64] row-major
    __shared__ float dsum[64];

    const int it = 15 - blockIdx.x;   // heavy tiles launch first
    const int bh = blockIdx.y;
    const int i0 = it * 64;

    const int tid = threadIdx.x;
    const int tx = tid & 15, ty = tid >> 4;

    // Load Q tile (transposed)
    const float* qsrc = g_qn + ((size_t)bh * N_ + i0) * D_;
    #pragma unroll
    for (int t = tid; t < 1024; t += 256) {
        int r = t >> 4, c = (t & 15) << 2;
        float4 x = *reinterpret_cast<const float4*>(qsrc + r * D_ + c);
        Qt[(c + 0) * 65 + r] = x.x; Qt[(c + 1) * 65 + r] = x.y;
        Qt[(c + 2) * 65 + r] = x.z; Qt[(c + 3) * 65 + r] = x.w;
    }

    const float* qrp = g_qr + (size_t)bh * N_ * N_;

    float o[4][4] = {};
    float dp[4] = {};

    for (int jt = 0; jt <= it; jt++) {
        const int j0 = jt * 64;
        const float* ksrc = g_kn + ((size_t)bh * N_ + j0) * D_;
        const float* vsrc = g_vp + ((size_t)bh * N_ + j0) * D_;

        // Load K (transposed) + V tiles. Prior sync at loop end guards reuse.
        #pragma unroll
        for (int t = tid; t < 1024; t += 256) {
            int r = t >> 4, c = (t & 15) << 2;
            float4 x = *reinterpret_cast<const float4*>(ksrc + r * D_ + c);
            Kt[(c + 0) * 65 + r] = x.x; Kt[(c + 1) * 65 + r] = x.y;
            Kt[(c + 2) * 65 + r] = x.z; Kt[(c + 3) * 65 + r] = x.w;
            float4 y = *reinterpret_cast<const float4*>(vsrc + r * D_ + c);
            *reinterpret_cast<float4*>(&Vs[r * 64 + c]) = y;
        }

        // Prefetch bias values (hidden under GEMM1)
        float qrv[4][4];
        #pragma unroll
        for (int u = 0; u < 4; u++) {
            int gi = i0 + 4 * ty + u;
            #pragma unroll
            for (int w = 0; w < 4; w++) {
                int gj = j0 + 4 * tx + w;
                qrv[u][w] = (gj <= gi) ? __ldg(qrp + (size_t)gi * N_ + (gi - gj)) : 0.0f;
            }
        }
        __syncthreads();

        // GEMM1: s = Q . K^T
        float s[4][4] = {};
        #pragma unroll 8
        for (int kk = 0; kk < 64; kk++) {
            float a[4], b[4];
            #pragma unroll
            for (int u = 0; u < 4; u++) a[u] = Qt[kk * 65 + 4 * ty + u];
            #pragma unroll
            for (int w = 0; w < 4; w++) b[w] = Kt[kk * 65 + 4 * tx + w];
            #pragma unroll
            for (int u = 0; u < 4; u++)
                #pragma unroll
                for (int w = 0; w < 4; w++)
                    s[u][w] = fmaf(a[u], b[w], s[u][w]);
        }

        // epilogue: bias + 1 + causal mask, stage scores in smem, denom partials
        #pragma unroll
        for (int u = 0; u < 4; u++) {
            int gi = i0 + 4 * ty + u;
            #pragma unroll
            for (int w = 0; w < 4; w++) {
                int gj = j0 + 4 * tx + w;
                float val = (gj <= gi) ? (s[u][w] + 1.0f + qrv[u][w]) : 0.0f;
                Ss[(4 * ty + u) * 65 + 4 * tx + w] = val;
                dp[u] += val;
            }
        }
        __syncthreads();

        // GEMM2: o += S . V
        #pragma unroll 8
        for (int jj = 0; jj < 64; jj++) {
            float sa[4], vb[4];
            #pragma unroll
            for (int u = 0; u < 4; u++) sa[u] = Ss[(4 * ty + u) * 65 + jj];
            #pragma unroll
            for (int w = 0; w < 4; w++) vb[w] = Vs[jj * 64 + 4 * tx + w];
            #pragma unroll
            for (int u = 0; u < 4; u++)
                #pragma unroll
                for (int w = 0; w < 4; w++)
                    o[u][w] = fmaf(sa[u], vb[w], o[u][w]);
        }
        __syncthreads();
    }

    // denominator reduction across tx (reuse Ss)
    #pragma unroll
    for (int u = 0; u < 4; u++) Ss[tx * 64 + 4 * ty + u] = dp[u];
    __syncthreads();
    if (tid < 64) {
        float ssum = 0.0f;
        #pragma unroll
        for (int x = 0; x < 16; x++) ssum += Ss[x * 64 + tid];
        dsum[tid] = 1.0f / ssum;
    }
    __syncthreads();

    #pragma unroll
    for (int u = 0; u < 4; u++) {
        float r = dsum[4 * ty + u];
        float4 o4 = make_float4(o[u][0] * r, o[u][1] * r, o[u][2] * r, o[u][3] * r);
        *reinterpret_cast<float4*>(out + ((size_t)bh * N_ + i0 + 4 * ty + u) * D_ + 4 * tx) = o4;
    }
}

// ---------------------------------------------------------------------------
extern "C" void kernel_launch(void* const* d_in, const int* in_sizes, int n_in,
                              void* d_out, int out_size) {
    const float* q   = (const float*)d_in[0];
    const float* k   = (const float*)d_in[1];
    const float* v   = (const float*)d_in[2];
    const float* dn  = (const float*)d_in[3];
    const float* rpe = (const float*)d_in[4];
    float* out = (float*)d_out;

    // normalize q and k: 2*BH*N rows, 8 rows (warps) per 256-thread block
    prep_norm_kernel<<<(2 * BH_ * N_) / 8, 256>>>(q, k);
    // v + 0.1*noise: BH*N*D/4 float4 elements
    prep_v_kernel<<<(BH_ * N_ * D_ / 4) / 256, 256>>>(v, dn);
    // QR precompute
    qr_kernel<<<dim3(16, 16, BH_), 256>>>(rpe);
    // main fused attention
    const int smem_bytes = 16576 * sizeof(float);  // 66304 B
    cudaFuncSetAttribute(fastmax_main_kernel,
                         cudaFuncAttributeMaxDynamicSharedMemorySize, smem_bytes);
    fastmax_main_kernel<<<dim3(16, BH_), 256, smem_bytes>>>(out);
}